// round 9
// baseline (speedup 1.0000x reference)
#include <cuda_runtime.h>
#include <cuda_fp16.h>
#include <cstdint>
#include <math.h>

#define NHEADS 16
#define SEQ    2048
#define EMB    1024
#define NBATCH 2
#define DHEAD  64

// Scratch (allocation-free rule): device globals. All fp16.
__device__ __half g_q[NBATCH * NHEADS * SEQ * DHEAD];     // [B,H,S,D]
__device__ __half g_k[NBATCH * NHEADS * SEQ * DHEAD];     // [B,H,S,D]
__device__ __half g_v[NBATCH * NHEADS * SEQ * DHEAD];     // [B,H,D,S]  (transposed!)
__device__ __half g_ctx[NBATCH * SEQ * EMB];              // [B,S,E]
__device__ __half g_xh[NBATCH * SEQ * EMB];
__device__ __half g_wk[EMB * EMB];
__device__ __half g_wq[EMB * EMB];
__device__ __half g_wv[EMB * EMB];
__device__ __half g_wu[EMB * EMB];

// ===========================================================================
// helpers
// ===========================================================================
__device__ __forceinline__ void mma_f16(float c[4], const uint32_t a[4], const uint32_t b[2]) {
    asm volatile(
        "mma.sync.aligned.m16n8k16.row.col.f32.f16.f16.f32 "
        "{%0,%1,%2,%3}, {%4,%5,%6,%7}, {%8,%9}, {%0,%1,%2,%3};"
        : "+f"(c[0]), "+f"(c[1]), "+f"(c[2]), "+f"(c[3])
        : "r"(a[0]), "r"(a[1]), "r"(a[2]), "r"(a[3]), "r"(b[0]), "r"(b[1]));
}
__device__ __forceinline__ uint32_t pack2(float lo, float hi) {
    __half2 h = __floats2half2_rn(lo, hi);
    return *(uint32_t*)&h;
}
__device__ __forceinline__ void cp16(uint32_t saddr, const void* gptr) {
    asm volatile("cp.async.cg.shared.global [%0], [%1], 16;" :: "r"(saddr), "l"(gptr));
}
#define CP_COMMIT() asm volatile("cp.async.commit_group;" ::: "memory")
#define CP_WAIT(n)  asm volatile("cp.async.wait_group %0;" :: "n"(n) : "memory")
__device__ __forceinline__ uint32_t smem_u32(const void* p) {
    uint32_t a;
    asm("{ .reg .u64 t; cvta.to.shared.u64 t, %1; cvt.u32.u64 %0, t; }" : "=r"(a) : "l"(p));
    return a;
}

// ===========================================================================
// Pre-round inputs to fp16 (RNE). 2M float4 total: 1M x, 4 x 256K weights.
// ===========================================================================
__global__ __launch_bounds__(256) void preround(const float4* __restrict__ x,
                                                const float4* __restrict__ wk,
                                                const float4* __restrict__ wq,
                                                const float4* __restrict__ wv,
                                                const float4* __restrict__ wu) {
    int i = blockIdx.x * 256 + threadIdx.x;
    const float4* src;
    __half2* dst;
    if (i < 1048576) {
        src = x + i;
        dst = (__half2*)g_xh + i * 2;
    } else {
        int j = i - 1048576;
        int w = j >> 18;
        int l = j & 262143;
        if (w == 0)      { src = wk + l; dst = (__half2*)g_wk + l * 2; }
        else if (w == 1) { src = wq + l; dst = (__half2*)g_wq + l * 2; }
        else if (w == 2) { src = wv + l; dst = (__half2*)g_wv + l * 2; }
        else             { src = wu + l; dst = (__half2*)g_wu + l * 2; }
    }
    float4 v = *src;
    dst[0] = __floats2half2_rn(v.x, v.y);
    dst[1] = __floats2half2_rn(v.z, v.w);
}

// ===========================================================================
// fp16 tensor-core NT GEMM: C[m,n] = sum_k A[m,k]*B[n,k]. M=4096,N=1024,K=1024.
// m16n8k16 fragments cp.async'd DIRECTLY into frag layout.
//   A chunk (row r, k16-step s): 32B = [k0..7 -> reg (rr>>3)] [k8..15 -> reg+2]
//   B chunk (row n, s): 32B = [k0..7 -> b0] [k8..15 -> b1]
// K-chunk 64 (4 s-steps), 16 iters, 3-stage pipeline, 2 groups in flight.
// 256 thr, 8 warps, warp tile 64x32.
// MODE 0: z selects Wq/Wk/Wv; Q,K -> [B,H,S,D]; V -> [B,H,D,S] transposed.
// MODE 1: row-major fp32 + bias.
// ===========================================================================
#define GK          1024
#define KT          64
#define NKT         (GK / KT)
#define STAGE_BYTES 32768
#define B_REG_OFF   16384
#define NSTAGE      3
#define GEMM_SMEM   (NSTAGE * STAGE_BYTES)   // 98304

struct GemmLd {
    int offA[2][2], offB[2][2];   // [js][half] smem byte offsets (stage-rel)
    int gA[2][2], gB[2][2];       // gmem half-elem offsets (row-rel, chunk-rel)
};

__device__ __forceinline__ void gemm_issue(uint32_t smb, int kt, const GemmLd& L,
                                           const __half* ApR, const __half* BpR) {
    uint32_t base = smb + (kt % NSTAGE) * STAGE_BYTES;
    const __half* Ap = ApR + kt * KT;
    const __half* Bp = BpR + kt * KT;
#pragma unroll
    for (int js = 0; js < 2; js++)
#pragma unroll
        for (int hf = 0; hf < 2; hf++) {
            cp16(base + L.offA[js][hf], Ap + L.gA[js][hf]);
            cp16(base + L.offB[js][hf], Bp + L.gB[js][hf]);
        }
}

template <int MODE>
__global__ __launch_bounds__(256) void gemm_tc(const __half* __restrict__ A,
                                               const __half* __restrict__ B0,
                                               const __half* __restrict__ B1,
                                               const __half* __restrict__ B2,
                                               __half* __restrict__ C0,
                                               __half* __restrict__ C1,
                                               __half* __restrict__ C2,
                                               float* __restrict__ Cf,
                                               const float* __restrict__ bias) {
    extern __shared__ char sma[];
    const uint32_t smb = smem_u32(sma);
    const int tid = threadIdx.x;
    const int wid = tid >> 5;
    const int lane = tid & 31;
    const int m0 = blockIdx.y * 128;
    const int n0 = blockIdx.x * 128;
    const int wm = (wid >> 2) * 64;
    const int wn = (wid & 3) * 32;
    const int z = blockIdx.z;
    const __half* Bm = (MODE == 1) ? B0 : ((z == 0) ? B0 : (z == 1) ? B1 : B2);

    // loader: thread t -> row r = t>>1 of A and B, s-pair (t&1)
    const int r = tid >> 1;
    const int s0 = (tid & 1) * 2;
    const __half* ApR = A  + (size_t)(m0 + r) * GK;
    const __half* BpR = Bm + (size_t)(n0 + r) * GK;

    GemmLd L;
    {
        const int mt = r >> 4, rr = r & 15, gA = rr & 7, hi = rr >> 3;
        const int ntB = r >> 3, gB = r & 7;
#pragma unroll
        for (int js = 0; js < 2; js++) {
            int s = s0 + js;
#pragma unroll
            for (int hf = 0; hf < 2; hf++) {
                L.offA[js][hf] = ((mt * 4 + s) * 4 + hi + 2 * hf) * 128 + gA * 16;
                L.offB[js][hf] = B_REG_OFF + ((ntB * 4 + s) * 2 + hf) * 128 + gB * 16;
                L.gA[js][hf] = s * 16 + hf * 8;
                L.gB[js][hf] = s * 16 + hf * 8;
            }
        }
    }

    float acc[4][4][4];
#pragma unroll
    for (int i = 0; i < 4; i++)
#pragma unroll
        for (int j = 0; j < 4; j++)
#pragma unroll
            for (int q = 0; q < 4; q++) acc[i][j][q] = 0.f;

    gemm_issue(smb, 0, L, ApR, BpR);
    CP_COMMIT();
    gemm_issue(smb, 1, L, ApR, BpR);
    CP_COMMIT();

    const int mtg0 = wm >> 4;
    const int ntg0 = wn >> 3;

    for (int kt = 0; kt < NKT; kt++) {
        if (kt + 2 < NKT) gemm_issue(smb, kt + 2, L, ApR, BpR);
        CP_COMMIT();
        CP_WAIT(2);
        __syncthreads();

        const char* buf = sma + (kt % NSTAGE) * STAGE_BYTES;
#pragma unroll
        for (int s = 0; s < 4; s++) {
            uint32_t afr[4][4], bfr[4][2];
#pragma unroll
            for (int mt = 0; mt < 4; mt++) {
                const uint32_t* base = (const uint32_t*)(buf + ((mtg0 + mt) * 4 + s) * 4 * 128);
#pragma unroll
                for (int q = 0; q < 4; q++) afr[mt][q] = base[q * 32 + lane];
            }
#pragma unroll
            for (int nt = 0; nt < 4; nt++) {
                const uint32_t* base =
                    (const uint32_t*)(buf + B_REG_OFF + ((ntg0 + nt) * 4 + s) * 2 * 128);
#pragma unroll
                for (int q = 0; q < 2; q++) bfr[nt][q] = base[q * 32 + lane];
            }
#pragma unroll
            for (int mt = 0; mt < 4; mt++)
#pragma unroll
                for (int nt = 0; nt < 4; nt++)
                    mma_f16(acc[mt][nt], afr[mt], bfr[nt]);
        }
        __syncthreads();
    }

    const int g = lane >> 2;
    const int tg = lane & 3;
#pragma unroll
    for (int mt = 0; mt < 4; mt++) {
#pragma unroll
        for (int rh = 0; rh < 2; rh++) {
            const int m = m0 + wm + mt * 16 + g + rh * 8;
#pragma unroll
            for (int nt = 0; nt < 4; nt++) {
                const int n = n0 + wn + nt * 8 + tg * 2;
                float v0 = acc[mt][nt][rh * 2 + 0];
                float v1 = acc[mt][nt][rh * 2 + 1];
                if (MODE == 0) {
                    const int bb = m >> 11, ss = m & 2047;
                    const int hh = n >> 6,  dd = n & 63;
                    if (z < 2) {
                        __half* C = (z == 0) ? C0 : C1;
                        __half2 hv = __floats2half2_rn(v0, v1);
                        *(__half2*)&C[(((size_t)bb * NHEADS + hh) * SEQ + ss) * DHEAD + dd] = hv;
                    } else {  // V: transposed [B,H,D,S]
                        __half* C = C2;
                        size_t base = ((size_t)bb * NHEADS + hh) * DHEAD;
                        C[(base + dd) * SEQ + ss]     = __float2half_rn(v0);
                        C[(base + dd + 1) * SEQ + ss] = __float2half_rn(v1);
                    }
                } else {
                    float* dst = Cf + (size_t)m * EMB + n;
                    *(float2*)dst = make_float2(v0 + bias[n], v1 + bias[n + 1]);
                }
            }
        }
    }
}

// ===========================================================================
// fp16 tensor-core causal flash attention.
// CTA 256 Q rows, 8 warps x 32-row tile (MT=2). KV tiles of 64 double-buffered.
// K from [B,H,S,D]; V from [B,H,D,S] (pre-transposed) — both land frag-direct.
// P c-fragments map 1:1 onto A-fragments: no smem, no syncwarp for P.
// ===========================================================================
#define KTILE_B   8192
#define AK_OFF(p) ((p) * KTILE_B)
#define AV_OFF(p) (2 * KTILE_B + (p) * KTILE_B)
#define ATTN_SMEM (4 * KTILE_B)

__device__ __forceinline__ void attn_load_tile(uint32_t smb, int tid, int buf,
                                               const __half* kb, const __half* vtb, int jt) {
    const int r = tid >> 2;      // 0..63 (seq row for K, d row for Vt)
    const int s = tid & 3;
    const int nt = r >> 3, gg = r & 7;
    uint32_t kdst = smb + AK_OFF(buf) + ((nt * 4 + s) * 2) * 128 + gg * 16;
    uint32_t vdst = smb + AV_OFF(buf) + ((nt * 4 + s) * 2) * 128 + gg * 16;
    const __half* kg = kb + (size_t)r * DHEAD + s * 16;
    const __half* vg = vtb + (size_t)r * SEQ + jt * 64 + s * 16;
    cp16(kdst, kg);
    cp16(kdst + 128, kg + 8);
    cp16(vdst, vg);
    cp16(vdst + 128, vg + 8);
    CP_COMMIT();
}

__global__ __launch_bounds__(256) void attn_tc(const __half* __restrict__ Q,
                                               const __half* __restrict__ Kg,
                                               const __half* __restrict__ Vt,
                                               __half* __restrict__ ctx) {
    extern __shared__ char sma[];
    const uint32_t smb = smem_u32(sma);
    const int tid  = threadIdx.x;
    const int wid  = tid >> 5;
    const int lane = tid & 31;
    const int g    = lane >> 2;
    const int tg   = lane & 3;
    const int blkE = gridDim.x - 1 - blockIdx.x;
    const int h = blockIdx.y;
    const int b = blockIdx.z;
    const int wrow = blkE * 256 + wid * 32;

    const __half* qb  = Q  + (((size_t)b * NHEADS + h) * SEQ + wrow) * DHEAD;
    const __half* kb0 = Kg + (((size_t)b * NHEADS + h) * SEQ) * DHEAD;
    const __half* vtb = Vt + (((size_t)b * NHEADS + h) * DHEAD) * SEQ;

    // Q A-fragments (m16n8k16): qf[mt][s][4], pre-scaled by 1/sqrt(D)=0.125 (exact)
    uint32_t qf[2][4][4];
    {
        const __half2 sc = __floats2half2_rn(0.125f, 0.125f);
        const __half2* q2 = (const __half2*)qb;
#pragma unroll
        for (int mt = 0; mt < 2; mt++)
#pragma unroll
            for (int s = 0; s < 4; s++) {
                __half2 h0 = __hmul2(q2[(mt * 16 + g) * 32 + s * 8 + tg], sc);
                __half2 h1 = __hmul2(q2[(mt * 16 + g + 8) * 32 + s * 8 + tg], sc);
                __half2 h2 = __hmul2(q2[(mt * 16 + g) * 32 + s * 8 + tg + 4], sc);
                __half2 h3 = __hmul2(q2[(mt * 16 + g + 8) * 32 + s * 8 + tg + 4], sc);
                qf[mt][s][0] = *(uint32_t*)&h0;
                qf[mt][s][1] = *(uint32_t*)&h1;
                qf[mt][s][2] = *(uint32_t*)&h2;
                qf[mt][s][3] = *(uint32_t*)&h3;
            }
    }

    float oacc[2][8][4];
#pragma unroll
    for (int mt = 0; mt < 2; mt++)
#pragma unroll
        for (int nt = 0; nt < 8; nt++)
#pragma unroll
            for (int q = 0; q < 4; q++) oacc[mt][nt][q] = 0.f;
    float m_[2][2] = {{-1e30f, -1e30f}, {-1e30f, -1e30f}};
    float l_[2][2] = {{0.f, 0.f}, {0.f, 0.f}};

    const int nT = 4 * blkE + 4;
    attn_load_tile(smb, tid, 0, kb0, vtb, 0);

    for (int jt = 0; jt < nT; jt++) {
        const int p = jt & 1;
        if (jt + 1 < nT) {
            attn_load_tile(smb, tid, 1 - p, kb0 + (size_t)(jt + 1) * 64 * DHEAD, vtb, jt + 1);
            CP_WAIT(1);
        } else {
            CP_WAIT(0);
        }
        __syncthreads();

        if (jt * 64 <= wrow + 31) {
            const char* Ks = sma + AK_OFF(p);
            const char* Vs = sma + AV_OFF(p);

            // ---- S = Q K^T ----
            float sacc[2][8][4];
#pragma unroll
            for (int mt = 0; mt < 2; mt++)
#pragma unroll
                for (int nt = 0; nt < 8; nt++)
#pragma unroll
                    for (int q = 0; q < 4; q++) sacc[mt][nt][q] = 0.f;

#pragma unroll
            for (int s = 0; s < 4; s++) {
#pragma unroll
                for (int nt = 0; nt < 8; nt++) {
                    const uint32_t* base = (const uint32_t*)(Ks + ((nt * 4 + s) * 2) * 128);
                    uint32_t bb[2] = {base[lane], base[32 + lane]};
                    mma_f16(sacc[0][nt], qf[0][s], bb);
                    mma_f16(sacc[1][nt], qf[1][s], bb);
                }
            }

            // ---- causal mask ----
            if (jt * 64 + 63 > wrow) {
#pragma unroll
                for (int mt = 0; mt < 2; mt++)
#pragma unroll
                    for (int nt = 0; nt < 8; nt++) {
                        int colb = jt * 64 + nt * 8 + 2 * tg;
#pragma unroll
                        for (int rh = 0; rh < 2; rh++) {
                            int row = wrow + mt * 16 + g + 8 * rh;
                            if (colb > row)     sacc[mt][nt][rh * 2 + 0] = -1e30f;
                            if (colb + 1 > row) sacc[mt][nt][rh * 2 + 1] = -1e30f;
                        }
                    }
            }

            // ---- online softmax ----
#pragma unroll
            for (int mt = 0; mt < 2; mt++) {
                float rmax[2] = {-1e30f, -1e30f};
#pragma unroll
                for (int nt = 0; nt < 8; nt++)
#pragma unroll
                    for (int rh = 0; rh < 2; rh++)
                        rmax[rh] = fmaxf(rmax[rh],
                                         fmaxf(sacc[mt][nt][rh * 2], sacc[mt][nt][rh * 2 + 1]));
#pragma unroll
                for (int rh = 0; rh < 2; rh++) {
                    rmax[rh] = fmaxf(rmax[rh], __shfl_xor_sync(0xffffffffu, rmax[rh], 1));
                    rmax[rh] = fmaxf(rmax[rh], __shfl_xor_sync(0xffffffffu, rmax[rh], 2));
                }
                float alpha[2], rsum[2] = {0.f, 0.f};
#pragma unroll
                for (int rh = 0; rh < 2; rh++) {
                    float mnew = fmaxf(m_[mt][rh], rmax[rh]);
                    alpha[rh] = __expf(m_[mt][rh] - mnew);
                    m_[mt][rh] = mnew;
                }
#pragma unroll
                for (int nt = 0; nt < 8; nt++)
#pragma unroll
                    for (int rh = 0; rh < 2; rh++) {
                        float p0 = __expf(sacc[mt][nt][rh * 2 + 0] - m_[mt][rh]);
                        float p1 = __expf(sacc[mt][nt][rh * 2 + 1] - m_[mt][rh]);
                        sacc[mt][nt][rh * 2 + 0] = p0;
                        sacc[mt][nt][rh * 2 + 1] = p1;
                        rsum[rh] += p0 + p1;
                    }
#pragma unroll
                for (int rh = 0; rh < 2; rh++) {
                    rsum[rh] += __shfl_xor_sync(0xffffffffu, rsum[rh], 1);
                    rsum[rh] += __shfl_xor_sync(0xffffffffu, rsum[rh], 2);
                    l_[mt][rh] = l_[mt][rh] * alpha[rh] + rsum[rh];
                }
#pragma unroll
                for (int nt = 0; nt < 8; nt++)
#pragma unroll
                    for (int rh = 0; rh < 2; rh++) {
                        oacc[mt][nt][rh * 2 + 0] *= alpha[rh];
                        oacc[mt][nt][rh * 2 + 1] *= alpha[rh];
                    }
            }

            // ---- O += P V : P c-frags pack directly into A-frags ----
#pragma unroll
            for (int s = 0; s < 4; s++) {   // k16-step over the 64 seq cols
                uint32_t pa[2][4];
#pragma unroll
                for (int mt = 0; mt < 2; mt++) {
                    pa[mt][0] = pack2(sacc[mt][2 * s][0],     sacc[mt][2 * s][1]);
                    pa[mt][1] = pack2(sacc[mt][2 * s][2],     sacc[mt][2 * s][3]);
                    pa[mt][2] = pack2(sacc[mt][2 * s + 1][0], sacc[mt][2 * s + 1][1]);
                    pa[mt][3] = pack2(sacc[mt][2 * s + 1][2], sacc[mt][2 * s + 1][3]);
                }
#pragma unroll
                for (int ntd = 0; ntd < 8; ntd++) {
                    const uint32_t* base = (const uint32_t*)(Vs + ((ntd * 4 + s) * 2) * 128);
                    uint32_t bb[2] = {base[lane], base[32 + lane]};
                    mma_f16(oacc[0][ntd], pa[0], bb);
                    mma_f16(oacc[1][ntd], pa[1], bb);
                }
            }
        }
        __syncthreads();
    }

    // ---- epilogue: O / l -> ctx [B,S,E] fp16 ----
#pragma unroll
    for (int mt = 0; mt < 2; mt++) {
        float inv[2] = {1.f / l_[mt][0], 1.f / l_[mt][1]};
#pragma unroll
        for (int rh = 0; rh < 2; rh++) {
            const int r = wrow + mt * 16 + g + 8 * rh;
            __half* dst = ctx + ((size_t)b * SEQ + r) * EMB + h * DHEAD + 2 * tg;
#pragma unroll
            for (int nt = 0; nt < 8; nt++) {
                __half2 hv = __floats2half2_rn(oacc[mt][nt][rh * 2 + 0] * inv[rh],
                                               oacc[mt][nt][rh * 2 + 1] * inv[rh]);
                *(__half2*)(dst + nt * 8) = hv;
            }
        }
    }
}

// ---------------------------------------------------------------------------
extern "C" void kernel_launch(void* const* d_in, const int* in_sizes, int n_in,
                              void* d_out, int out_size) {
    const float* x  = (const float*)d_in[0];
    const float* Wk = (const float*)d_in[1];
    const float* Wq = (const float*)d_in[2];
    const float* Wv = (const float*)d_in[3];
    const float* Wu = (const float*)d_in[4];
    const float* bu = (const float*)d_in[5];
    float* out = (float*)d_out;

    __half *qp, *kp, *vp, *cp, *xh, *wk, *wq, *wv, *wu;
    cudaGetSymbolAddress((void**)&qp, g_q);
    cudaGetSymbolAddress((void**)&kp, g_k);
    cudaGetSymbolAddress((void**)&vp, g_v);
    cudaGetSymbolAddress((void**)&cp, g_ctx);
    cudaGetSymbolAddress((void**)&xh, g_xh);
    cudaGetSymbolAddress((void**)&wk, g_wk);
    cudaGetSymbolAddress((void**)&wq, g_wq);
    cudaGetSymbolAddress((void**)&wv, g_wv);
    cudaGetSymbolAddress((void**)&wu, g_wu);

    cudaFuncSetAttribute(gemm_tc<0>, cudaFuncAttributeMaxDynamicSharedMemorySize, GEMM_SMEM);
    cudaFuncSetAttribute(gemm_tc<1>, cudaFuncAttributeMaxDynamicSharedMemorySize, GEMM_SMEM);
    cudaFuncSetAttribute(attn_tc, cudaFuncAttributeMaxDynamicSharedMemorySize, ATTN_SMEM);

    preround<<<8192, 256>>>((const float4*)x, (const float4*)Wk, (const float4*)Wq,
                            (const float4*)Wv, (const float4*)Wu);

    dim3 gqkv(EMB / 128, (NBATCH * SEQ) / 128, 3);
    gemm_tc<0><<<gqkv, 256, GEMM_SMEM>>>(xh, wq, wk, wv, qp, kp, vp, nullptr, nullptr);

    attn_tc<<<dim3(SEQ / 256, NHEADS, NBATCH), 256, ATTN_SMEM>>>(qp, kp, vp, cp);

    dim3 go(EMB / 128, (NBATCH * SEQ) / 128, 1);
    gemm_tc<1><<<go, 256, GEMM_SMEM>>>(cp, wu, nullptr, nullptr,
                                       nullptr, nullptr, nullptr, out, bu);
}

// round 10
// speedup vs baseline: 1.6693x; 1.6693x over previous
#include <cuda_runtime.h>
#include <cuda_fp16.h>
#include <cstdint>

#define NHEADS 16
#define SEQ    2048
#define EMB    1024
#define NBATCH 2
#define DHEAD  64

// Fragment-ordered gmem files (device globals; allocation-free rule).
__device__ __half g_xh[NBATCH * SEQ * EMB];    // A-frag file [mb 32][kt 16][16KB]
__device__ __half g_ctx[NBATCH * SEQ * EMB];   // A-frag file (written by attention)
__device__ __half g_wk[EMB * EMB];             // B-frag file [nb 8][kt 16][16KB]
__device__ __half g_wq[EMB * EMB];
__device__ __half g_wv[EMB * EMB];
__device__ __half g_wu[EMB * EMB];
__device__ __half g_q[NBATCH * NHEADS * SEQ * DHEAD];  // [B,H,S,D] linear
__device__ __half g_k[NBATCH * NHEADS * SEQ * DHEAD];  // per (b,h): 32 x 8KB B-frag tiles (n=seq,k=d)
__device__ __half g_v[NBATCH * NHEADS * SEQ * DHEAD];  // per (b,h): 32 x 8KB B-frag tiles (n=d,k=seq)

// ---------------------------------------------------------------------------
__device__ __forceinline__ void mma_f16(float c[4], const uint32_t a[4], const uint32_t b[2]) {
    asm volatile(
        "mma.sync.aligned.m16n8k16.row.col.f32.f16.f16.f32 "
        "{%0,%1,%2,%3}, {%4,%5,%6,%7}, {%8,%9}, {%0,%1,%2,%3};"
        : "+f"(c[0]), "+f"(c[1]), "+f"(c[2]), "+f"(c[3])
        : "r"(a[0]), "r"(a[1]), "r"(a[2]), "r"(a[3]), "r"(b[0]), "r"(b[1]));
}
__device__ __forceinline__ uint32_t pack2(float lo, float hi) {
    __half2 h = __floats2half2_rn(lo, hi);
    return *(uint32_t*)&h;
}
__device__ __forceinline__ uint32_t smem_u32(const void* p) {
    uint32_t a;
    asm("{ .reg .u64 t; cvta.to.shared.u64 t, %1; cvt.u32.u64 %0, t; }" : "=r"(a) : "l"(p));
    return a;
}
#define MBAR_INIT(addr, cnt) \
    asm volatile("mbarrier.init.shared.b64 [%0], %1;" :: "r"(addr), "r"(cnt) : "memory")
#define MBAR_EXPECT(addr, bytes) \
    asm volatile("mbarrier.arrive.expect_tx.shared.b64 _, [%0], %1;" :: "r"(addr), "r"(bytes) : "memory")
#define MBAR_WAIT(addr, par) do {                                              \
    uint32_t _m = (addr), _p = (par), _d;                                      \
    asm volatile("{ .reg .pred p; mbarrier.try_wait.parity.acquire.cta.shared::cta.b64 p, [%1], %2; selp.b32 %0,1,0,p; }" \
        : "=r"(_d) : "r"(_m), "r"(_p) : "memory");                             \
    while (!_d)                                                                \
        asm volatile("{ .reg .pred p; mbarrier.try_wait.parity.acquire.cta.shared::cta.b64 p, [%1], %2, 0x989680; selp.b32 %0,1,0,p; }" \
            : "=r"(_d) : "r"(_m), "r"(_p) : "memory");                         \
} while (0)
__device__ __forceinline__ void bulk_cp(uint32_t dst, const void* src, uint32_t n, uint32_t mbar) {
    asm volatile(
        "cp.async.bulk.shared::cluster.global.mbarrier::complete_tx::bytes [%0], [%1], %2, [%3];"
        :: "r"(dst), "l"(src), "r"(n), "r"(mbar) : "memory");
}

// Fragment-file byte offsets (tiles 128x64 A / 128x64 B, 16KB each).
__device__ __forceinline__ int frag_a_off(int m, int k, int ktiles) {
    int mb = m >> 7, r = m & 127, mt = r >> 4, rr = r & 15;
    int s = (k >> 4) & 3, hf = (k & 15) >> 3, tg = (k & 7) >> 1;
    return (mb * ktiles + (k >> 6)) * 16384 +
           ((mt * 4 + s) * 4 + (rr >> 3) + 2 * hf) * 128 + ((rr & 7) * 4 + tg) * 4 + (k & 1) * 2;
}
__device__ __forceinline__ int frag_b_off(int n, int k, int ktiles) {
    int nb = n >> 7, rn = n & 127;
    int s = (k >> 4) & 3, hf = (k & 15) >> 3, tg = (k & 7) >> 1;
    return (nb * ktiles + (k >> 6)) * 16384 +
           (((rn >> 3) * 4 + s) * 2 + hf) * 128 + ((rn & 7) * 4 + tg) * 4 + (k & 1) * 2;
}
// 64x64 B-frag tile (8KB), tile-internal offset
__device__ __forceinline__ int tile_b_off(int n, int k) {
    int s = k >> 4, hf = (k & 15) >> 3, tg = (k & 7) >> 1;
    return (((n >> 3) * 4 + s) * 2 + hf) * 128 + ((n & 7) * 4 + tg) * 4 + (k & 1) * 2;
}

// ===========================================================================
// Preround: fp32 -> fp16 + permute into fragment files. One float4 / thread.
// ===========================================================================
__global__ __launch_bounds__(256) void preround(const float4* __restrict__ x,
                                                const float4* __restrict__ wk,
                                                const float4* __restrict__ wq,
                                                const float4* __restrict__ wv,
                                                const float4* __restrict__ wu) {
    int i = blockIdx.x * 256 + threadIdx.x;
    float4 v;
    char* dst;
    if (i < 1048576) {
        v = x[i];
        dst = (char*)g_xh + frag_a_off(i >> 8, (i & 255) * 4, 16);
    } else {
        int j = i - 1048576, w = j >> 18, l = j & 262143;
        const float4* src = (w == 0) ? wk : (w == 1) ? wq : (w == 2) ? wv : wu;
        char* base = (char*)((w == 0) ? g_wk : (w == 1) ? g_wq : (w == 2) ? g_wv : g_wu);
        v = src[l];
        dst = base + frag_b_off(l >> 8, (l & 255) * 4, 16);
    }
    *(uint2*)dst = make_uint2(pack2(v.x, v.y), pack2(v.z, v.w));
}

// ===========================================================================
// fp16 NT GEMM, bulk-copy pipeline. CTA 128x128, 8 warps (64x32), 16 K-iters,
// 3 stages x 32KB, mbarrier/stage, 2 x 16KB cp.async.bulk per stage by tid0.
// MODE 0: z->Wq/Wk/Wv; Q->[B,H,S,D]; K,V->attention B-frag tile files.
// MODE 1: fp32 + bias.
// ===========================================================================
#define NKT       16
#define STG_B     32768
#define MB_OFF    (3 * STG_B)
#define GEMM_SMEM (MB_OFF + 32)

template <int MODE>
__global__ __launch_bounds__(256) void gemm_tc(const char* __restrict__ Af,
                                               const char* __restrict__ Bw0,
                                               const char* __restrict__ Bw1,
                                               const char* __restrict__ Bw2,
                                               __half* __restrict__ Cq,
                                               __half* __restrict__ Ck,
                                               __half* __restrict__ Cv,
                                               float* __restrict__ Cf,
                                               const float* __restrict__ bias) {
    extern __shared__ char sma[];
    const uint32_t smb = smem_u32(sma);
    const int tid = threadIdx.x, wid = tid >> 5, lane = tid & 31;
    const int z = blockIdx.z;
    const int wm = (wid >> 2) * 64, wn = (wid & 3) * 32;
    const char* Bf = (MODE == 1) ? Bw0 : ((z == 0) ? Bw0 : (z == 1) ? Bw1 : Bw2);
    const char* Ab = Af + (size_t)blockIdx.y * 16 * 16384;
    const char* Bb = Bf + (size_t)blockIdx.x * 16 * 16384;

    if (tid == 0) {
        MBAR_INIT(smb + MB_OFF + 0, 1);
        MBAR_INIT(smb + MB_OFF + 8, 1);
        MBAR_INIT(smb + MB_OFF + 16, 1);
    }
    __syncthreads();
#define G_ISSUE(kt) do { int _st = (kt) % 3; uint32_t _mb = smb + MB_OFF + _st * 8;      \
        MBAR_EXPECT(_mb, 32768u);                                                        \
        bulk_cp(smb + _st * STG_B,         Ab + (size_t)(kt) * 16384, 16384u, _mb);      \
        bulk_cp(smb + _st * STG_B + 16384, Bb + (size_t)(kt) * 16384, 16384u, _mb); } while (0)
    if (tid == 0) { G_ISSUE(0); G_ISSUE(1); }

    float acc[4][4][4];
#pragma unroll
    for (int i = 0; i < 4; i++)
#pragma unroll
        for (int j = 0; j < 4; j++)
#pragma unroll
            for (int q = 0; q < 4; q++) acc[i][j][q] = 0.f;

    const int mtg0 = wm >> 4, ntg0 = wn >> 3;
    for (int kt = 0; kt < NKT; kt++) {
        if (tid == 0 && kt + 2 < NKT) G_ISSUE(kt + 2);
        const int st = kt % 3;
        MBAR_WAIT(smb + MB_OFF + st * 8, (uint32_t)((kt / 3) & 1));

        const char* buf = sma + st * STG_B;
#pragma unroll
        for (int s = 0; s < 4; s++) {
            uint32_t afr[4][4], bfr[4][2];
#pragma unroll
            for (int mt = 0; mt < 4; mt++) {
                const uint32_t* b = (const uint32_t*)(buf + ((mtg0 + mt) * 4 + s) * 512);
#pragma unroll
                for (int q = 0; q < 4; q++) afr[mt][q] = b[q * 32 + lane];
            }
#pragma unroll
            for (int nt = 0; nt < 4; nt++) {
                const uint32_t* b = (const uint32_t*)(buf + 16384 + ((ntg0 + nt) * 4 + s) * 256);
#pragma unroll
                for (int q = 0; q < 2; q++) bfr[nt][q] = b[q * 32 + lane];
            }
#pragma unroll
            for (int mt = 0; mt < 4; mt++)
#pragma unroll
                for (int nt = 0; nt < 4; nt++)
                    mma_f16(acc[mt][nt], afr[mt], bfr[nt]);
        }
        __syncthreads();
    }

    const int g = lane >> 2, tg = lane & 3;
#pragma unroll
    for (int mt = 0; mt < 4; mt++)
#pragma unroll
        for (int rh = 0; rh < 2; rh++) {
            const int m = blockIdx.y * 128 + wm + mt * 16 + g + rh * 8;
#pragma unroll
            for (int nt = 0; nt < 4; nt++) {
                const int n = blockIdx.x * 128 + wn + nt * 8 + tg * 2;
                float v0 = acc[mt][nt][rh * 2], v1 = acc[mt][nt][rh * 2 + 1];
                if (MODE == 0) {
                    const int bb = m >> 11, ss = m & 2047, hh = n >> 6, dd = n & 63;
                    if (z == 0) {
                        *(__half2*)&Cq[(((size_t)bb * NHEADS + hh) * SEQ + ss) * DHEAD + dd] =
                            __floats2half2_rn(v0, v1);
                    } else if (z == 1) {   // K tile: n=seq row, k=d
                        char* base = (char*)Ck + (((size_t)bb * NHEADS + hh) * 32 + (ss >> 6)) * 8192;
                        *(uint32_t*)(base + tile_b_off(ss & 63, dd)) = pack2(v0, v1);
                    } else {               // V tile: n=d row, k=seq
                        char* base = (char*)Cv + (((size_t)bb * NHEADS + hh) * 32 + (ss >> 6)) * 8192;
                        *(__half*)(base + tile_b_off(dd,     ss & 63)) = __float2half_rn(v0);
                        *(__half*)(base + tile_b_off(dd + 1, ss & 63)) = __float2half_rn(v1);
                    }
                } else {
                    *(float2*)&Cf[(size_t)m * EMB + n] =
                        make_float2(v0 + bias[n], v1 + bias[n + 1]);
                }
            }
        }
}

// ===========================================================================
// fp16 causal flash attention, bulk K/V loads from frag-tile files.
// CTA 256 Q rows, 8 warps x 32 rows (MT=2). 2 stages x 16KB + 2 mbarriers.
// ctx written into A-frag file for the output GEMM.
// ===========================================================================
#define AT_MB    (2 * 16384)
#define ATTN_SMEM (AT_MB + 16)

__global__ __launch_bounds__(256) void attn_tc(const __half* __restrict__ Q,
                                               const __half* __restrict__ Kf,
                                               const __half* __restrict__ Vf,
                                               __half* __restrict__ ctx) {
    extern __shared__ char sma[];
    const uint32_t smb = smem_u32(sma);
    const int tid = threadIdx.x, wid = tid >> 5, lane = tid & 31;
    const int g = lane >> 2, tg = lane & 3;
    const int blkE = gridDim.x - 1 - blockIdx.x;
    const int h = blockIdx.y, b = blockIdx.z;
    const int wrow = blkE * 256 + wid * 32;

    const __half* qb = Q + (((size_t)b * NHEADS + h) * SEQ + wrow) * DHEAD;
    const char* kb = (const char*)Kf + ((size_t)b * NHEADS + h) * 32 * 8192;
    const char* vb = (const char*)Vf + ((size_t)b * NHEADS + h) * 32 * 8192;

    uint32_t qf[2][4][4];
    {
        const __half2 sc = __floats2half2_rn(0.125f, 0.125f);
        const __half2* q2 = (const __half2*)qb;
#pragma unroll
        for (int mt = 0; mt < 2; mt++)
#pragma unroll
            for (int s = 0; s < 4; s++) {
                __half2 h0 = __hmul2(q2[(mt * 16 + g) * 32 + s * 8 + tg], sc);
                __half2 h1 = __hmul2(q2[(mt * 16 + g + 8) * 32 + s * 8 + tg], sc);
                __half2 h2 = __hmul2(q2[(mt * 16 + g) * 32 + s * 8 + tg + 4], sc);
                __half2 h3 = __hmul2(q2[(mt * 16 + g + 8) * 32 + s * 8 + tg + 4], sc);
                qf[mt][s][0] = *(uint32_t*)&h0;
                qf[mt][s][1] = *(uint32_t*)&h1;
                qf[mt][s][2] = *(uint32_t*)&h2;
                qf[mt][s][3] = *(uint32_t*)&h3;
            }
    }

    float oacc[2][8][4];
#pragma unroll
    for (int mt = 0; mt < 2; mt++)
#pragma unroll
        for (int nt = 0; nt < 8; nt++)
#pragma unroll
            for (int q = 0; q < 4; q++) oacc[mt][nt][q] = 0.f;
    float m_[2][2] = {{-1e30f, -1e30f}, {-1e30f, -1e30f}};
    float l_[2][2] = {{0.f, 0.f}, {0.f, 0.f}};

    if (tid == 0) {
        MBAR_INIT(smb + AT_MB + 0, 1);
        MBAR_INIT(smb + AT_MB + 8, 1);
    }
    __syncthreads();
#define A_ISSUE(jt) do { int _p = (jt) & 1; uint32_t _mb = smb + AT_MB + _p * 8;     \
        MBAR_EXPECT(_mb, 16384u);                                                    \
        bulk_cp(smb + _p * 16384,        kb + (size_t)(jt) * 8192, 8192u, _mb);      \
        bulk_cp(smb + _p * 16384 + 8192, vb + (size_t)(jt) * 8192, 8192u, _mb); } while (0)
    const int nT = 4 * blkE + 4;
    if (tid == 0) A_ISSUE(0);

    for (int jt = 0; jt < nT; jt++) {
        const int p = jt & 1;
        if (tid == 0 && jt + 1 < nT) A_ISSUE(jt + 1);
        MBAR_WAIT(smb + AT_MB + p * 8, (uint32_t)((jt / 2) & 1));

        if (jt * 64 <= wrow + 31) {
            const char* Ks = sma + p * 16384;
            const char* Vs = Ks + 8192;

            float sacc[2][8][4];
#pragma unroll
            for (int mt = 0; mt < 2; mt++)
#pragma unroll
                for (int nt = 0; nt < 8; nt++)
#pragma unroll
                    for (int q = 0; q < 4; q++) sacc[mt][nt][q] = 0.f;

#pragma unroll
            for (int s = 0; s < 4; s++)
#pragma unroll
                for (int nt = 0; nt < 8; nt++) {
                    const uint32_t* bp = (const uint32_t*)(Ks + ((nt * 4 + s) * 2) * 128);
                    uint32_t bb2[2] = {bp[lane], bp[32 + lane]};
                    mma_f16(sacc[0][nt], qf[0][s], bb2);
                    mma_f16(sacc[1][nt], qf[1][s], bb2);
                }

            if (jt * 64 + 63 > wrow) {
#pragma unroll
                for (int mt = 0; mt < 2; mt++)
#pragma unroll
                    for (int nt = 0; nt < 8; nt++) {
                        int colb = jt * 64 + nt * 8 + 2 * tg;
#pragma unroll
                        for (int rh = 0; rh < 2; rh++) {
                            int row = wrow + mt * 16 + g + 8 * rh;
                            if (colb > row)     sacc[mt][nt][rh * 2 + 0] = -1e30f;
                            if (colb + 1 > row) sacc[mt][nt][rh * 2 + 1] = -1e30f;
                        }
                    }
            }

#pragma unroll
            for (int mt = 0; mt < 2; mt++) {
                float rmax[2] = {-1e30f, -1e30f};
#pragma unroll
                for (int nt = 0; nt < 8; nt++)
#pragma unroll
                    for (int rh = 0; rh < 2; rh++)
                        rmax[rh] = fmaxf(rmax[rh],
                                         fmaxf(sacc[mt][nt][rh * 2], sacc[mt][nt][rh * 2 + 1]));
#pragma unroll
                for (int rh = 0; rh < 2; rh++) {
                    rmax[rh] = fmaxf(rmax[rh], __shfl_xor_sync(0xffffffffu, rmax[rh], 1));
                    rmax[rh] = fmaxf(rmax[rh], __shfl_xor_sync(0xffffffffu, rmax[rh], 2));
                }
                float alpha[2], rsum[2] = {0.f, 0.f};
#pragma unroll
                for (int rh = 0; rh < 2; rh++) {
                    float mnew = fmaxf(m_[mt][rh], rmax[rh]);
                    alpha[rh] = __expf(m_[mt][rh] - mnew);
                    m_[mt][rh] = mnew;
                }
#pragma unroll
                for (int nt = 0; nt < 8; nt++)
#pragma unroll
                    for (int rh = 0; rh < 2; rh++) {
                        float p0 = __expf(sacc[mt][nt][rh * 2 + 0] - m_[mt][rh]);
                        float p1 = __expf(sacc[mt][nt][rh * 2 + 1] - m_[mt][rh]);
                        sacc[mt][nt][rh * 2 + 0] = p0;
                        sacc[mt][nt][rh * 2 + 1] = p1;
                        rsum[rh] += p0 + p1;
                    }
#pragma unroll
                for (int rh = 0; rh < 2; rh++) {
                    rsum[rh] += __shfl_xor_sync(0xffffffffu, rsum[rh], 1);
                    rsum[rh] += __shfl_xor_sync(0xffffffffu, rsum[rh], 2);
                    l_[mt][rh] = l_[mt][rh] * alpha[rh] + rsum[rh];
                }
#pragma unroll
                for (int nt = 0; nt < 8; nt++)
#pragma unroll
                    for (int rh = 0; rh < 2; rh++) {
                        oacc[mt][nt][rh * 2 + 0] *= alpha[rh];
                        oacc[mt][nt][rh * 2 + 1] *= alpha[rh];
                    }
            }

#pragma unroll
            for (int s = 0; s < 4; s++) {
                uint32_t pa[2][4];
#pragma unroll
                for (int mt = 0; mt < 2; mt++) {
                    pa[mt][0] = pack2(sacc[mt][2 * s][0],     sacc[mt][2 * s][1]);
                    pa[mt][1] = pack2(sacc[mt][2 * s][2],     sacc[mt][2 * s][3]);
                    pa[mt][2] = pack2(sacc[mt][2 * s + 1][0], sacc[mt][2 * s + 1][1]);
                    pa[mt][3] = pack2(sacc[mt][2 * s + 1][2], sacc[mt][2 * s + 1][3]);
                }
#pragma unroll
                for (int ntd = 0; ntd < 8; ntd++) {
                    const uint32_t* bp = (const uint32_t*)(Vs + ((ntd * 4 + s) * 2) * 128);
                    uint32_t bb2[2] = {bp[lane], bp[32 + lane]};
                    mma_f16(oacc[0][ntd], pa[0], bb2);
                    mma_f16(oacc[1][ntd], pa[1], bb2);
                }
            }
        }
        __syncthreads();
    }

    // epilogue: O/l -> ctx A-frag file
#pragma unroll
    for (int mt = 0; mt < 2; mt++) {
        float inv[2] = {1.f / l_[mt][0], 1.f / l_[mt][1]};
#pragma unroll
        for (int rh = 0; rh < 2; rh++) {
            const int m = b * SEQ + wrow + mt * 16 + g + 8 * rh;
#pragma unroll
            for (int nt = 0; nt < 8; nt++) {
                int k = h * DHEAD + nt * 8 + 2 * tg;
                *(uint32_t*)((char*)ctx + frag_a_off(m, k, 16)) =
                    pack2(oacc[mt][nt][rh * 2] * inv[rh], oacc[mt][nt][rh * 2 + 1] * inv[rh]);
            }
        }
    }
}

// ---------------------------------------------------------------------------
extern "C" void kernel_launch(void* const* d_in, const int* in_sizes, int n_in,
                              void* d_out, int out_size) {
    const float* x  = (const float*)d_in[0];
    const float* Wk = (const float*)d_in[1];
    const float* Wq = (const float*)d_in[2];
    const float* Wv = (const float*)d_in[3];
    const float* Wu = (const float*)d_in[4];
    const float* bu = (const float*)d_in[5];
    float* out = (float*)d_out;

    __half *qp, *kp, *vp, *cp, *xh, *wk, *wq, *wv, *wu;
    cudaGetSymbolAddress((void**)&qp, g_q);
    cudaGetSymbolAddress((void**)&kp, g_k);
    cudaGetSymbolAddress((void**)&vp, g_v);
    cudaGetSymbolAddress((void**)&cp, g_ctx);
    cudaGetSymbolAddress((void**)&xh, g_xh);
    cudaGetSymbolAddress((void**)&wk, g_wk);
    cudaGetSymbolAddress((void**)&wq, g_wq);
    cudaGetSymbolAddress((void**)&wv, g_wv);
    cudaGetSymbolAddress((void**)&wu, g_wu);

    cudaFuncSetAttribute(gemm_tc<0>, cudaFuncAttributeMaxDynamicSharedMemorySize, GEMM_SMEM);
    cudaFuncSetAttribute(gemm_tc<1>, cudaFuncAttributeMaxDynamicSharedMemorySize, GEMM_SMEM);
    cudaFuncSetAttribute(attn_tc, cudaFuncAttributeMaxDynamicSharedMemorySize, ATTN_SMEM);

    preround<<<8192, 256>>>((const float4*)x, (const float4*)Wk, (const float4*)Wq,
                            (const float4*)Wv, (const float4*)Wu);

    dim3 gqkv(EMB / 128, (NBATCH * SEQ) / 128, 3);
    gemm_tc<0><<<gqkv, 256, GEMM_SMEM>>>((const char*)xh, (const char*)wq, (const char*)wk,
                                         (const char*)wv, qp, kp, vp, nullptr, nullptr);

    attn_tc<<<dim3(SEQ / 256, NHEADS, NBATCH), 256, ATTN_SMEM>>>(qp, kp, vp, cp);

    dim3 go(EMB / 128, (NBATCH * SEQ) / 128, 1);
    gemm_tc<1><<<go, 256, GEMM_SMEM>>>((const char*)cp, (const char*)wu, nullptr, nullptr,
                                       nullptr, nullptr, nullptr, out, bu);
}

// round 11
// speedup vs baseline: 1.7555x; 1.0516x over previous
#include <cuda_runtime.h>
#include <cuda_fp16.h>
#include <cstdint>

#define NHEADS 16
#define SEQ    2048
#define EMB    1024
#define NBATCH 2
#define DHEAD  64

// Fragment-ordered gmem files (device globals; allocation-free rule).
__device__ __half g_xh[NBATCH * SEQ * EMB];    // A-frag file [mb 32][kt 16][16KB]
__device__ __half g_ctx[NBATCH * SEQ * EMB];   // A-frag file (written by attention)
__device__ __half g_wk[EMB * EMB];             // B-frag file [nb 8][kt 16][16KB]
__device__ __half g_wq[EMB * EMB];
__device__ __half g_wv[EMB * EMB];
__device__ __half g_wu[EMB * EMB];
__device__ __half g_q[NBATCH * NHEADS * SEQ * DHEAD];  // [B,H,S,D] linear
__device__ __half g_k[NBATCH * NHEADS * SEQ * DHEAD];  // per (b,h): 32 x 8KB B-frag tiles (n=seq,k=d)
__device__ __half g_v[NBATCH * NHEADS * SEQ * DHEAD];  // per (b,h): 32 x 8KB B-frag tiles (n=d,k=seq)

// ---------------------------------------------------------------------------
__device__ __forceinline__ void mma_f16(float c[4], const uint32_t a[4], const uint32_t b[2]) {
    asm volatile(
        "mma.sync.aligned.m16n8k16.row.col.f32.f16.f16.f32 "
        "{%0,%1,%2,%3}, {%4,%5,%6,%7}, {%8,%9}, {%0,%1,%2,%3};"
        : "+f"(c[0]), "+f"(c[1]), "+f"(c[2]), "+f"(c[3])
        : "r"(a[0]), "r"(a[1]), "r"(a[2]), "r"(a[3]), "r"(b[0]), "r"(b[1]));
}
__device__ __forceinline__ uint32_t pack2(float lo, float hi) {
    __half2 h = __floats2half2_rn(lo, hi);
    return *(uint32_t*)&h;
}
__device__ __forceinline__ uint32_t smem_u32(const void* p) {
    uint32_t a;
    asm("{ .reg .u64 t; cvta.to.shared.u64 t, %1; cvt.u32.u64 %0, t; }" : "=r"(a) : "l"(p));
    return a;
}
#define MBAR_INIT(addr, cnt) \
    asm volatile("mbarrier.init.shared.b64 [%0], %1;" :: "r"(addr), "r"(cnt) : "memory")
#define MBAR_EXPECT(addr, bytes) \
    asm volatile("mbarrier.arrive.expect_tx.shared.b64 _, [%0], %1;" :: "r"(addr), "r"(bytes) : "memory")
#define MBAR_WAIT(addr, par) do {                                              \
    uint32_t _m = (addr), _p = (par), _d;                                      \
    asm volatile("{ .reg .pred p; mbarrier.try_wait.parity.acquire.cta.shared::cta.b64 p, [%1], %2; selp.b32 %0,1,0,p; }" \
        : "=r"(_d) : "r"(_m), "r"(_p) : "memory");                             \
    while (!_d)                                                                \
        asm volatile("{ .reg .pred p; mbarrier.try_wait.parity.acquire.cta.shared::cta.b64 p, [%1], %2, 0x989680; selp.b32 %0,1,0,p; }" \
            : "=r"(_d) : "r"(_m), "r"(_p) : "memory");                         \
} while (0)
__device__ __forceinline__ void bulk_cp(uint32_t dst, const void* src, uint32_t n, uint32_t mbar) {
    asm volatile(
        "cp.async.bulk.shared::cluster.global.mbarrier::complete_tx::bytes [%0], [%1], %2, [%3];"
        :: "r"(dst), "l"(src), "r"(n), "r"(mbar) : "memory");
}

// Lane-major fragment-file byte offsets.
// A tile 128x64 (16KB): (mt,s) blocks of 512B, within: lane*16 + reg*4 + lo*2
// B tile 128x64 (16KB): (nt,s) blocks of 256B, within: lane*8 + reg*4 + lo*2
__device__ __forceinline__ int frag_a_off(int m, int k, int ktiles) {
    int mb = m >> 7, r = m & 127, mt = r >> 4, rr = r & 15;
    int s = (k >> 4) & 3, hf = (k & 15) >> 3, tg = (k & 7) >> 1;
    return (mb * ktiles + (k >> 6)) * 16384 + (mt * 4 + s) * 512 +
           ((rr & 7) * 4 + tg) * 16 + ((rr >> 3) + 2 * hf) * 4 + (k & 1) * 2;
}
__device__ __forceinline__ int frag_b_off(int n, int k, int ktiles) {
    int nb = n >> 7, rn = n & 127;
    int s = (k >> 4) & 3, hf = (k & 15) >> 3, tg = (k & 7) >> 1;
    return (nb * ktiles + (k >> 6)) * 16384 + ((rn >> 3) * 4 + s) * 256 +
           ((rn & 7) * 4 + tg) * 8 + hf * 4 + (k & 1) * 2;
}
// 64x64 B-frag tile (8KB), tile-internal offset
__device__ __forceinline__ int tile_b_off(int n, int k) {
    int s = k >> 4, hf = (k & 15) >> 3, tg = (k & 7) >> 1;
    return ((n >> 3) * 4 + s) * 256 + ((n & 7) * 4 + tg) * 8 + hf * 4 + (k & 1) * 2;
}

// ===========================================================================
// Preround: fp32 -> fp16 + permute into fragment files. One float4 / thread.
// (k,k+1) contiguous 4B; (k+2,k+3) in the next lane slot -> two 4B stores.
// ===========================================================================
__global__ __launch_bounds__(256) void preround(const float4* __restrict__ x,
                                                const float4* __restrict__ wk,
                                                const float4* __restrict__ wq,
                                                const float4* __restrict__ wv,
                                                const float4* __restrict__ wu) {
    int i = blockIdx.x * 256 + threadIdx.x;
    float4 v;
    char* base;
    int o0, o1;
    if (i < 1048576) {
        v = x[i];
        int m = i >> 8, k = (i & 255) * 4;
        base = (char*)g_xh;
        o0 = frag_a_off(m, k, 16);
        o1 = frag_a_off(m, k + 2, 16);
    } else {
        int j = i - 1048576, w = j >> 18, l = j & 262143;
        const float4* src = (w == 0) ? wk : (w == 1) ? wq : (w == 2) ? wv : wu;
        base = (char*)((w == 0) ? g_wk : (w == 1) ? g_wq : (w == 2) ? g_wv : g_wu);
        v = src[l];
        int n = l >> 8, k = (l & 255) * 4;
        o0 = frag_b_off(n, k, 16);
        o1 = frag_b_off(n, k + 2, 16);
    }
    *(uint32_t*)(base + o0) = pack2(v.x, v.y);
    *(uint32_t*)(base + o1) = pack2(v.z, v.w);
}

// ===========================================================================
// fp16 NT GEMM, bulk-copy pipeline + vectorized fragment LDS.
// CTA 128x128, 8 warps (64x32), 16 K-iters, 3 stages x 32KB, mbarrier/stage.
// MODE 0: z->Wq/Wk/Wv; Q->[B,H,S,D]; K,V->attention B-frag tile files.
// MODE 1: fp32 + bias.
// ===========================================================================
#define NKT       16
#define STG_B     32768
#define MB_OFF    (3 * STG_B)
#define GEMM_SMEM (MB_OFF + 32)

template <int MODE>
__global__ __launch_bounds__(256) void gemm_tc(const char* __restrict__ Af,
                                               const char* __restrict__ Bw0,
                                               const char* __restrict__ Bw1,
                                               const char* __restrict__ Bw2,
                                               __half* __restrict__ Cq,
                                               __half* __restrict__ Ck,
                                               __half* __restrict__ Cv,
                                               float* __restrict__ Cf,
                                               const float* __restrict__ bias) {
    extern __shared__ char sma[];
    const uint32_t smb = smem_u32(sma);
    const int tid = threadIdx.x, wid = tid >> 5, lane = tid & 31;
    const int z = blockIdx.z;
    const int wm = (wid >> 2) * 64, wn = (wid & 3) * 32;
    const char* Bf = (MODE == 1) ? Bw0 : ((z == 0) ? Bw0 : (z == 1) ? Bw1 : Bw2);
    const char* Ab = Af + (size_t)blockIdx.y * 16 * 16384;
    const char* Bb = Bf + (size_t)blockIdx.x * 16 * 16384;

    if (tid == 0) {
        MBAR_INIT(smb + MB_OFF + 0, 1);
        MBAR_INIT(smb + MB_OFF + 8, 1);
        MBAR_INIT(smb + MB_OFF + 16, 1);
    }
    __syncthreads();
#define G_ISSUE(kt) do { int _st = (kt) % 3; uint32_t _mb = smb + MB_OFF + _st * 8;      \
        MBAR_EXPECT(_mb, 32768u);                                                        \
        bulk_cp(smb + _st * STG_B,         Ab + (size_t)(kt) * 16384, 16384u, _mb);      \
        bulk_cp(smb + _st * STG_B + 16384, Bb + (size_t)(kt) * 16384, 16384u, _mb); } while (0)
    if (tid == 0) { G_ISSUE(0); G_ISSUE(1); }

    float acc[4][4][4];
#pragma unroll
    for (int i = 0; i < 4; i++)
#pragma unroll
        for (int j = 0; j < 4; j++)
#pragma unroll
            for (int q = 0; q < 4; q++) acc[i][j][q] = 0.f;

    const int mtg0 = wm >> 4, ntg0 = wn >> 3;
    for (int kt = 0; kt < NKT; kt++) {
        if (tid == 0 && kt + 2 < NKT) G_ISSUE(kt + 2);
        const int st = kt % 3;
        MBAR_WAIT(smb + MB_OFF + st * 8, (uint32_t)((kt / 3) & 1));

        const char* buf = sma + st * STG_B;
#pragma unroll
        for (int s = 0; s < 4; s++) {
            uint32_t afr[4][4], bfr[4][2];
#pragma unroll
            for (int mt = 0; mt < 4; mt++) {
                uint4 va = *(const uint4*)(buf + ((mtg0 + mt) * 4 + s) * 512 + lane * 16);
                afr[mt][0] = va.x; afr[mt][1] = va.y; afr[mt][2] = va.z; afr[mt][3] = va.w;
            }
#pragma unroll
            for (int nt = 0; nt < 4; nt++) {
                uint2 vb = *(const uint2*)(buf + 16384 + ((ntg0 + nt) * 4 + s) * 256 + lane * 8);
                bfr[nt][0] = vb.x; bfr[nt][1] = vb.y;
            }
#pragma unroll
            for (int mt = 0; mt < 4; mt++)
#pragma unroll
                for (int nt = 0; nt < 4; nt++)
                    mma_f16(acc[mt][nt], afr[mt], bfr[nt]);
        }
        __syncthreads();
    }

    const int g = lane >> 2, tg = lane & 3;
#pragma unroll
    for (int mt = 0; mt < 4; mt++)
#pragma unroll
        for (int rh = 0; rh < 2; rh++) {
            const int m = blockIdx.y * 128 + wm + mt * 16 + g + rh * 8;
#pragma unroll
            for (int nt = 0; nt < 4; nt++) {
                const int n = blockIdx.x * 128 + wn + nt * 8 + tg * 2;
                float v0 = acc[mt][nt][rh * 2], v1 = acc[mt][nt][rh * 2 + 1];
                if (MODE == 0) {
                    const int bb = m >> 11, ss = m & 2047, hh = n >> 6, dd = n & 63;
                    if (z == 0) {
                        *(__half2*)&Cq[(((size_t)bb * NHEADS + hh) * SEQ + ss) * DHEAD + dd] =
                            __floats2half2_rn(v0, v1);
                    } else if (z == 1) {   // K tile: n=seq row, k=d
                        char* base = (char*)Ck + (((size_t)bb * NHEADS + hh) * 32 + (ss >> 6)) * 8192;
                        *(uint32_t*)(base + tile_b_off(ss & 63, dd)) = pack2(v0, v1);
                    } else {               // V tile: n=d row, k=seq
                        char* base = (char*)Cv + (((size_t)bb * NHEADS + hh) * 32 + (ss >> 6)) * 8192;
                        *(__half*)(base + tile_b_off(dd,     ss & 63)) = __float2half_rn(v0);
                        *(__half*)(base + tile_b_off(dd + 1, ss & 63)) = __float2half_rn(v1);
                    }
                } else {
                    *(float2*)&Cf[(size_t)m * EMB + n] =
                        make_float2(v0 + bias[n], v1 + bias[n + 1]);
                }
            }
        }
}

// ===========================================================================
// fp16 causal flash attention, bulk K/V loads + vectorized fragment LDS.
// CTA 256 Q rows, 8 warps x 32 rows (MT=2). 2 stages x 16KB + 2 mbarriers.
// ===========================================================================
#define AT_MB     (2 * 16384)
#define ATTN_SMEM (AT_MB + 16)

__global__ __launch_bounds__(256) void attn_tc(const __half* __restrict__ Q,
                                               const __half* __restrict__ Kf,
                                               const __half* __restrict__ Vf,
                                               __half* __restrict__ ctx) {
    extern __shared__ char sma[];
    const uint32_t smb = smem_u32(sma);
    const int tid = threadIdx.x, wid = tid >> 5, lane = tid & 31;
    const int g = lane >> 2, tg = lane & 3;
    const int blkE = gridDim.x - 1 - blockIdx.x;
    const int h = blockIdx.y, b = blockIdx.z;
    const int wrow = blkE * 256 + wid * 32;

    const __half* qb = Q + (((size_t)b * NHEADS + h) * SEQ + wrow) * DHEAD;
    const char* kb = (const char*)Kf + ((size_t)b * NHEADS + h) * 32 * 8192;
    const char* vb = (const char*)Vf + ((size_t)b * NHEADS + h) * 32 * 8192;

    uint32_t qf[2][4][4];
    {
        const __half2 sc = __floats2half2_rn(0.125f, 0.125f);
        const __half2* q2 = (const __half2*)qb;
#pragma unroll
        for (int mt = 0; mt < 2; mt++)
#pragma unroll
            for (int s = 0; s < 4; s++) {
                __half2 h0 = __hmul2(q2[(mt * 16 + g) * 32 + s * 8 + tg], sc);
                __half2 h1 = __hmul2(q2[(mt * 16 + g + 8) * 32 + s * 8 + tg], sc);
                __half2 h2 = __hmul2(q2[(mt * 16 + g) * 32 + s * 8 + tg + 4], sc);
                __half2 h3 = __hmul2(q2[(mt * 16 + g + 8) * 32 + s * 8 + tg + 4], sc);
                qf[mt][s][0] = *(uint32_t*)&h0;
                qf[mt][s][1] = *(uint32_t*)&h1;
                qf[mt][s][2] = *(uint32_t*)&h2;
                qf[mt][s][3] = *(uint32_t*)&h3;
            }
    }

    float oacc[2][8][4];
#pragma unroll
    for (int mt = 0; mt < 2; mt++)
#pragma unroll
        for (int nt = 0; nt < 8; nt++)
#pragma unroll
            for (int q = 0; q < 4; q++) oacc[mt][nt][q] = 0.f;
    float m_[2][2] = {{-1e30f, -1e30f}, {-1e30f, -1e30f}};
    float l_[2][2] = {{0.f, 0.f}, {0.f, 0.f}};

    if (tid == 0) {
        MBAR_INIT(smb + AT_MB + 0, 1);
        MBAR_INIT(smb + AT_MB + 8, 1);
    }
    __syncthreads();
#define A_ISSUE(jt) do { int _p = (jt) & 1; uint32_t _mb = smb + AT_MB + _p * 8;     \
        MBAR_EXPECT(_mb, 16384u);                                                    \
        bulk_cp(smb + _p * 16384,        kb + (size_t)(jt) * 8192, 8192u, _mb);      \
        bulk_cp(smb + _p * 16384 + 8192, vb + (size_t)(jt) * 8192, 8192u, _mb); } while (0)
    const int nT = 4 * blkE + 4;
    if (tid == 0) A_ISSUE(0);

    for (int jt = 0; jt < nT; jt++) {
        const int p = jt & 1;
        if (tid == 0 && jt + 1 < nT) A_ISSUE(jt + 1);
        MBAR_WAIT(smb + AT_MB + p * 8, (uint32_t)((jt / 2) & 1));

        if (jt * 64 <= wrow + 31) {
            const char* Ks = sma + p * 16384;
            const char* Vs = Ks + 8192;

            float sacc[2][8][4];
#pragma unroll
            for (int mt = 0; mt < 2; mt++)
#pragma unroll
                for (int nt = 0; nt < 8; nt++)
#pragma unroll
                    for (int q = 0; q < 4; q++) sacc[mt][nt][q] = 0.f;

#pragma unroll
            for (int s = 0; s < 4; s++)
#pragma unroll
                for (int nt = 0; nt < 8; nt++) {
                    uint2 vb2 = *(const uint2*)(Ks + ((nt * 4 + s) * 256) + lane * 8);
                    uint32_t bb2[2] = {vb2.x, vb2.y};
                    mma_f16(sacc[0][nt], qf[0][s], bb2);
                    mma_f16(sacc[1][nt], qf[1][s], bb2);
                }

            if (jt * 64 + 63 > wrow) {
#pragma unroll
                for (int mt = 0; mt < 2; mt++)
#pragma unroll
                    for (int nt = 0; nt < 8; nt++) {
                        int colb = jt * 64 + nt * 8 + 2 * tg;
#pragma unroll
                        for (int rh = 0; rh < 2; rh++) {
                            int row = wrow + mt * 16 + g + 8 * rh;
                            if (colb > row)     sacc[mt][nt][rh * 2 + 0] = -1e30f;
                            if (colb + 1 > row) sacc[mt][nt][rh * 2 + 1] = -1e30f;
                        }
                    }
            }

#pragma unroll
            for (int mt = 0; mt < 2; mt++) {
                float rmax[2] = {-1e30f, -1e30f};
#pragma unroll
                for (int nt = 0; nt < 8; nt++)
#pragma unroll
                    for (int rh = 0; rh < 2; rh++)
                        rmax[rh] = fmaxf(rmax[rh],
                                         fmaxf(sacc[mt][nt][rh * 2], sacc[mt][nt][rh * 2 + 1]));
#pragma unroll
                for (int rh = 0; rh < 2; rh++) {
                    rmax[rh] = fmaxf(rmax[rh], __shfl_xor_sync(0xffffffffu, rmax[rh], 1));
                    rmax[rh] = fmaxf(rmax[rh], __shfl_xor_sync(0xffffffffu, rmax[rh], 2));
                }
                float alpha[2], rsum[2] = {0.f, 0.f};
#pragma unroll
                for (int rh = 0; rh < 2; rh++) {
                    float mnew = fmaxf(m_[mt][rh], rmax[rh]);
                    alpha[rh] = __expf(m_[mt][rh] - mnew);
                    m_[mt][rh] = mnew;
                }
#pragma unroll
                for (int nt = 0; nt < 8; nt++)
#pragma unroll
                    for (int rh = 0; rh < 2; rh++) {
                        float p0 = __expf(sacc[mt][nt][rh * 2 + 0] - m_[mt][rh]);
                        float p1 = __expf(sacc[mt][nt][rh * 2 + 1] - m_[mt][rh]);
                        sacc[mt][nt][rh * 2 + 0] = p0;
                        sacc[mt][nt][rh * 2 + 1] = p1;
                        rsum[rh] += p0 + p1;
                    }
#pragma unroll
                for (int rh = 0; rh < 2; rh++) {
                    rsum[rh] += __shfl_xor_sync(0xffffffffu, rsum[rh], 1);
                    rsum[rh] += __shfl_xor_sync(0xffffffffu, rsum[rh], 2);
                    l_[mt][rh] = l_[mt][rh] * alpha[rh] + rsum[rh];
                }
#pragma unroll
                for (int nt = 0; nt < 8; nt++)
#pragma unroll
                    for (int rh = 0; rh < 2; rh++) {
                        oacc[mt][nt][rh * 2 + 0] *= alpha[rh];
                        oacc[mt][nt][rh * 2 + 1] *= alpha[rh];
                    }
            }

#pragma unroll
            for (int s = 0; s < 4; s++) {
                uint32_t pa[2][4];
#pragma unroll
                for (int mt = 0; mt < 2; mt++) {
                    pa[mt][0] = pack2(sacc[mt][2 * s][0],     sacc[mt][2 * s][1]);
                    pa[mt][1] = pack2(sacc[mt][2 * s][2],     sacc[mt][2 * s][3]);
                    pa[mt][2] = pack2(sacc[mt][2 * s + 1][0], sacc[mt][2 * s + 1][1]);
                    pa[mt][3] = pack2(sacc[mt][2 * s + 1][2], sacc[mt][2 * s + 1][3]);
                }
#pragma unroll
                for (int ntd = 0; ntd < 8; ntd++) {
                    uint2 vb2 = *(const uint2*)(Vs + ((ntd * 4 + s) * 256) + lane * 8);
                    uint32_t bb2[2] = {vb2.x, vb2.y};
                    mma_f16(oacc[0][ntd], pa[0], bb2);
                    mma_f16(oacc[1][ntd], pa[1], bb2);
                }
            }
        }
        __syncthreads();
    }

    // epilogue: O/l -> ctx A-frag file
#pragma unroll
    for (int mt = 0; mt < 2; mt++) {
        float inv[2] = {1.f / l_[mt][0], 1.f / l_[mt][1]};
#pragma unroll
        for (int rh = 0; rh < 2; rh++) {
            const int m = b * SEQ + wrow + mt * 16 + g + 8 * rh;
#pragma unroll
            for (int nt = 0; nt < 8; nt++) {
                int k = h * DHEAD + nt * 8 + 2 * tg;
                *(uint32_t*)((char*)ctx + frag_a_off(m, k, 16)) =
                    pack2(oacc[mt][nt][rh * 2] * inv[rh], oacc[mt][nt][rh * 2 + 1] * inv[rh]);
            }
        }
    }
}

// ---------------------------------------------------------------------------
extern "C" void kernel_launch(void* const* d_in, const int* in_sizes, int n_in,
                              void* d_out, int out_size) {
    const float* x  = (const float*)d_in[0];
    const float* Wk = (const float*)d_in[1];
    const float* Wq = (const float*)d_in[2];
    const float* Wv = (const float*)d_in[3];
    const float* Wu = (const float*)d_in[4];
    const float* bu = (const float*)d_in[5];
    float* out = (float*)d_out;

    __half *qp, *kp, *vp, *cp, *xh, *wk, *wq, *wv, *wu;
    cudaGetSymbolAddress((void**)&qp, g_q);
    cudaGetSymbolAddress((void**)&kp, g_k);
    cudaGetSymbolAddress((void**)&vp, g_v);
    cudaGetSymbolAddress((void**)&cp, g_ctx);
    cudaGetSymbolAddress((void**)&xh, g_xh);
    cudaGetSymbolAddress((void**)&wk, g_wk);
    cudaGetSymbolAddress((void**)&wq, g_wq);
    cudaGetSymbolAddress((void**)&wv, g_wv);
    cudaGetSymbolAddress((void**)&wu, g_wu);

    cudaFuncSetAttribute(gemm_tc<0>, cudaFuncAttributeMaxDynamicSharedMemorySize, GEMM_SMEM);
    cudaFuncSetAttribute(gemm_tc<1>, cudaFuncAttributeMaxDynamicSharedMemorySize, GEMM_SMEM);
    cudaFuncSetAttribute(attn_tc, cudaFuncAttributeMaxDynamicSharedMemorySize, ATTN_SMEM);

    preround<<<8192, 256>>>((const float4*)x, (const float4*)Wk, (const float4*)Wq,
                            (const float4*)Wv, (const float4*)Wu);

    dim3 gqkv(EMB / 128, (NBATCH * SEQ) / 128, 3);
    gemm_tc<0><<<gqkv, 256, GEMM_SMEM>>>((const char*)xh, (const char*)wq, (const char*)wk,
                                         (const char*)wv, qp, kp, vp, nullptr, nullptr);

    attn_tc<<<dim3(SEQ / 256, NHEADS, NBATCH), 256, ATTN_SMEM>>>(qp, kp, vp, cp);

    dim3 go(EMB / 128, (NBATCH * SEQ) / 128, 1);
    gemm_tc<1><<<go, 256, GEMM_SMEM>>>((const char*)cp, (const char*)wu, nullptr, nullptr,
                                       nullptr, nullptr, nullptr, out, bu);
}